// round 8
// baseline (speedup 1.0000x reference)
#include <cuda_runtime.h>
#include <cstdint>

// Shapes (fixed by the problem)
#define B_ 2
#define S_ 1024
#define H_ 512
#define A_ 128

#define CTAS_PER_B 74            // 148 attn CTAs total, 13-14 rows each
#define MAXR 16
#define TJ 128
#define NT 8                     // S_/TJ tiles

// ---------------- scratch (no allocation allowed) ----------------
__device__ float g_wx [B_ * S_ * A_];        // [m=b*S+s][a]  row-major f32 (1 MB)
__device__ float g_uxt[B_ * A_ * S_];        // [b][a][s]     a-major f32 (1 MB)
__device__ float g_colsum[B_ * S_];

// packed half-precision tanh: 2 values through one MUFU op (f32 in/out)
__device__ __forceinline__ void tanh2_fast(float x0, float x1, float& t0, float& t1) {
    uint32_t h, h2;
    asm("cvt.rn.f16x2.f32 %0, %1, %2;" : "=r"(h) : "f"(x1), "f"(x0)); // lo=x0, hi=x1
    asm("tanh.approx.f16x2 %0, %1;" : "=r"(h2) : "r"(h));
    asm("{ .reg .b16 lo, hi;\n"
        "  mov.b32 {lo, hi}, %2;\n"
        "  cvt.f32.f16 %0, lo;\n"
        "  cvt.f32.f16 %1, hi; }"
        : "=f"(t0), "=f"(t1) : "r"(h2));
}

__device__ __forceinline__ void cp16(float* dst_smem, const float* src) {
    uint32_t d = (uint32_t)__cvta_generic_to_shared(dst_smem);
    asm volatile("cp.async.cg.shared.global [%0], [%1], 16;\n" :: "r"(d), "l"(src));
}
#define CP_COMMIT() asm volatile("cp.async.commit_group;\n")
#define CP_WAIT(N)  asm volatile("cp.async.wait_group %0;\n" :: "n"(N))

// ---------------- kernel 1: wx = lstm@w, uxt = (lstm@u)^T, fused zeroing ----------------
// BM=32 x BN=64, 128 threads, grid (64, 4) = 256 CTAs -> ~2 CTAs/SM
#define BK 16
__global__ __launch_bounds__(128) void gemm_wxux(
    const float* __restrict__ lstm, const float* __restrict__ w, const float* __restrict__ u,
    float* __restrict__ ctx)
{
    __shared__ float As[BK][32];
    __shared__ float Bs[BK][64];
    int tid = threadIdx.x;

    if (blockIdx.x == 0 && blockIdx.y == 0) {      // fused zeroing
        for (int t = tid; t < B_ * S_; t += 128) g_colsum[t] = 0.0f;
        for (int t = tid; t < B_ * H_; t += 128) ctx[t] = 0.0f;
    }

    int m0 = blockIdx.x * 32;                      // 64 blocks over m
    int n0 = blockIdx.y * 64;                      // 0,64 -> w ; 128,192 -> u
    const float* bsrc = (n0 < A_) ? (w + n0) : (u + (n0 - A_));

    int tm = (tid >> 4) * 4;                       // 0..28
    int tn = (tid & 15) * 4;                       // 0..60
    int la_m = tid >> 2;                           // 0..31
    int la_k = (tid & 3) * 4;                      // 0,4,8,12
    int lb_k = tid >> 4;                           // 0..7 (and +8)
    int lb_n = (tid & 15) * 4;                     // 0..60

    float acc[4][4];
#pragma unroll
    for (int i = 0; i < 4; i++)
#pragma unroll
        for (int j = 0; j < 4; j++) acc[i][j] = 0.0f;

    for (int k0 = 0; k0 < H_; k0 += BK) {
        float4 av  = *(const float4*)(lstm + (size_t)(m0 + la_m) * H_ + k0 + la_k);
        float4 bv0 = *(const float4*)(bsrc + (size_t)(k0 + lb_k) * A_ + lb_n);
        float4 bv1 = *(const float4*)(bsrc + (size_t)(k0 + lb_k + 8) * A_ + lb_n);
        __syncthreads();
        As[la_k + 0][la_m] = av.x;
        As[la_k + 1][la_m] = av.y;
        As[la_k + 2][la_m] = av.z;
        As[la_k + 3][la_m] = av.w;
        *(float4*)&Bs[lb_k][lb_n] = bv0;
        *(float4*)&Bs[lb_k + 8][lb_n] = bv1;
        __syncthreads();
#pragma unroll
        for (int kk = 0; kk < BK; kk++) {
            float4 a4 = *(const float4*)&As[kk][tm];
            float4 b4 = *(const float4*)&Bs[kk][tn];
            float am[4] = {a4.x, a4.y, a4.z, a4.w};
            float bn[4] = {b4.x, b4.y, b4.z, b4.w};
#pragma unroll
            for (int i = 0; i < 4; i++)
#pragma unroll
                for (int j = 0; j < 4; j++) acc[i][j] = fmaf(am[i], bn[j], acc[i][j]);
        }
    }

    if (n0 < A_) {
        // wx: row-major f32 [m][a]
#pragma unroll
        for (int i = 0; i < 4; i++) {
            float4 o = make_float4(acc[i][0], acc[i][1], acc[i][2], acc[i][3]);
            *(float4*)(g_wx + (size_t)(m0 + tm + i) * A_ + n0 + tn) = o;
        }
    } else {
        // ux: transposed f32 -> g_uxt[b][a][s] (float4 along s; s0 multiple of 4)
        int b  = m0 >> 10;
        int s0 = (m0 & (S_ - 1)) + tm;
        int a0 = (n0 - A_) + tn;
        float* base = g_uxt + (size_t)b * A_ * S_;
#pragma unroll
        for (int j = 0; j < 4; j++) {
            float4 o = make_float4(acc[0][j], acc[1][j], acc[2][j], acc[3][j]);
            *(float4*)(base + (size_t)(a0 + j) * S_ + s0) = o;
        }
    }
}

// ---------------- kernel 2: e via paired f16x2 tanh (all a), reg softmax, attn + colsum ----
// dyn smem: wx_s[16][128] + ux double buffer 2*[128][TJ] + v_s[128]  ~ 139.8 KB (f32, as R6)
__global__ __launch_bounds__(512) void attn_e_kernel(
    const float* __restrict__ v, float* __restrict__ attn_out)
{
    extern __shared__ float sm[];
    float* wx_s = sm;                          // MAXR*128
    float* ux0  = wx_s + MAXR * A_;            // 128*TJ buffer 0
    float* ux1  = ux0 + A_ * TJ;               // 128*TJ buffer 1
    float* v_s  = ux1 + A_ * TJ;               // 128

    int tid  = threadIdx.x;
    int warp = tid >> 5;
    int lane = tid & 31;
    int blk  = blockIdx.x;                     // 148 blocks
    int b    = blk / CTAS_PER_B;
    int t_   = blk % CTAS_PER_B;
    int i0   = (S_ * t_) / CTAS_PER_B;
    int i1   = (S_ * (t_ + 1)) / CTAS_PER_B;
    int nr   = i1 - i0;                        // 13 or 14

    const float* uxt_b = g_uxt + (size_t)b * A_ * S_;
    int pa = tid >> 5, pc = tid & 31;          // prefetch coords: 8 rows per thread

#pragma unroll
    for (int k = 0; k < 8; k++)
        cp16(ux0 + (pa + 16 * k) * TJ + 4 * pc, uxt_b + (size_t)(pa + 16 * k) * S_ + 4 * pc);
    CP_COMMIT();

    for (int x = tid; x < nr * (A_ / 4); x += 512) {
        int r = x >> 5, c = x & 31;
        *(float4*)(wx_s + r * A_ + 4 * c) =
            *(const float4*)(g_wx + (size_t)(b * S_ + i0 + r) * A_ + 4 * c);
    }
    if (tid < 32) ((float4*)v_s)[tid] = ((const float4*)v)[tid];

    bool active = (warp < nr);
    float er[4 * NT];

#pragma unroll
    for (int t = 0; t < NT; t++) {
        float* cur = (t & 1) ? ux1 : ux0;
        if (t + 1 < NT) {
            float* nxt = ((t + 1) & 1) ? ux1 : ux0;
            const float* src = uxt_b + (size_t)(t + 1) * TJ;
#pragma unroll
            for (int k = 0; k < 8; k++)
                cp16(nxt + (pa + 16 * k) * TJ + 4 * pc, src + (size_t)(pa + 16 * k) * S_ + 4 * pc);
            CP_COMMIT();
            CP_WAIT(1);
        } else {
            CP_WAIT(0);
        }
        __syncthreads();

        if (active) {
            float acc0 = 0.f, acc1 = 0.f, acc2 = 0.f, acc3 = 0.f;
            const float4* wr = (const float4*)(wx_s + warp * A_);
            const float4* vr = (const float4*)v_s;
            const float*  ub = cur + 4 * lane;

            // ALL a via paired f16x2 tanh (2 tanh per MUFU op) -- proven path from R6
#pragma unroll 4
            for (int a4 = 0; a4 < 32; a4++) {
                float4 w4 = wr[a4];
                float4 v4 = vr[a4];
                float4 uu0 = *(const float4*)(ub + (4 * a4 + 0) * TJ);
                float4 uu1 = *(const float4*)(ub + (4 * a4 + 1) * TJ);
                float4 uu2 = *(const float4*)(ub + (4 * a4 + 2) * TJ);
                float4 uu3 = *(const float4*)(ub + (4 * a4 + 3) * TJ);
                {
                    float t0, t1, t2, t3;
                    tanh2_fast(w4.x + uu0.x, w4.y + uu1.x, t0, t1);
                    tanh2_fast(w4.z + uu2.x, w4.w + uu3.x, t2, t3);
                    acc0 = fmaf(t0, v4.x, acc0); acc0 = fmaf(t1, v4.y, acc0);
                    acc0 = fmaf(t2, v4.z, acc0); acc0 = fmaf(t3, v4.w, acc0);
                }
                {
                    float t0, t1, t2, t3;
                    tanh2_fast(w4.x + uu0.y, w4.y + uu1.y, t0, t1);
                    tanh2_fast(w4.z + uu2.y, w4.w + uu3.y, t2, t3);
                    acc1 = fmaf(t0, v4.x, acc1); acc1 = fmaf(t1, v4.y, acc1);
                    acc1 = fmaf(t2, v4.z, acc1); acc1 = fmaf(t3, v4.w, acc1);
                }
                {
                    float t0, t1, t2, t3;
                    tanh2_fast(w4.x + uu0.z, w4.y + uu1.z, t0, t1);
                    tanh2_fast(w4.z + uu2.z, w4.w + uu3.z, t2, t3);
                    acc2 = fmaf(t0, v4.x, acc2); acc2 = fmaf(t1, v4.y, acc2);
                    acc2 = fmaf(t2, v4.z, acc2); acc2 = fmaf(t3, v4.w, acc2);
                }
                {
                    float t0, t1, t2, t3;
                    tanh2_fast(w4.x + uu0.w, w4.y + uu1.w, t0, t1);
                    tanh2_fast(w4.z + uu2.w, w4.w + uu3.w, t2, t3);
                    acc3 = fmaf(t0, v4.x, acc3); acc3 = fmaf(t1, v4.y, acc3);
                    acc3 = fmaf(t2, v4.z, acc3); acc3 = fmaf(t3, v4.w, acc3);
                }
            }

            er[4 * t + 0] = acc0;
            er[4 * t + 1] = acc1;
            er[4 * t + 2] = acc2;
            er[4 * t + 3] = acc3;
        }
        __syncthreads();
    }

    float* slots = ux0;
    if (active) {
        float m = er[0];
#pragma unroll
        for (int k = 1; k < 4 * NT; k++) m = fmaxf(m, er[k]);
#pragma unroll
        for (int o = 16; o; o >>= 1) m = fmaxf(m, __shfl_xor_sync(0xffffffffu, m, o));
        float s = 0.f;
#pragma unroll
        for (int k = 0; k < 4 * NT; k++) {
            er[k] = __expf(er[k] - m);
            s += er[k];
        }
#pragma unroll
        for (int o = 16; o; o >>= 1) s += __shfl_xor_sync(0xffffffffu, s, o);
        float inv = 1.0f / s;
        float* orow = attn_out + (size_t)(b * S_ + i0 + warp) * S_;
        float* srow = slots + (size_t)warp * S_;
#pragma unroll
        for (int ti = 0; ti < NT; ti++) {
            float4 o = make_float4(er[4 * ti] * inv, er[4 * ti + 1] * inv,
                                   er[4 * ti + 2] * inv, er[4 * ti + 3] * inv);
            *(float4*)(orow + ti * TJ + 4 * lane) = o;
            *(float4*)(srow + ti * TJ + 4 * lane) = o;
        }
    }
    __syncthreads();

    for (int j = tid; j < S_; j += 512) {
        float s = 0.f;
        for (int r = 0; r < nr; r++) s += slots[(size_t)r * S_ + j];
        atomicAdd(&g_colsum[b * S_ + j], s);
    }
}

// ---------------- kernel 3: context[b,h] = sum_j colsum[b,j] * lstm[b,j,h] ----------------
__global__ __launch_bounds__(512) void context_kernel(
    const float* __restrict__ lstm, float* __restrict__ ctx)
{
    int b  = blockIdx.x >> 6;                      // 2 * 64 blocks
    int j0 = (blockIdx.x & 63) * 16;
    int h  = threadIdx.x;
    __shared__ float cs[16];
    if (threadIdx.x < 16) cs[threadIdx.x] = g_colsum[b * S_ + j0 + threadIdx.x];
    __syncthreads();
    float acc = 0.f;
    const float* lp = lstm + ((size_t)(b * S_ + j0)) * H_ + h;
#pragma unroll
    for (int j = 0; j < 16; j++) acc = fmaf(cs[j], lp[(size_t)j * H_], acc);
    atomicAdd(&ctx[b * H_ + h], acc);
}

// ---------------- launch (single stream, deterministic) ----------------
extern "C" void kernel_launch(void* const* d_in, const int* in_sizes, int n_in,
                              void* d_out, int out_size)
{
    const float* lstm = (const float*)d_in[0];
    const float* w    = (const float*)d_in[1];
    const float* u    = (const float*)d_in[2];
    const float* v    = (const float*)d_in[3];
    float* out  = (float*)d_out;
    float* ctx  = out;                // (B,H) = 1024 floats first
    float* attn = out + B_ * H_;      // (B,S,S) = 2M floats after

    gemm_wxux<<<dim3(64, 4), 128>>>(lstm, w, u, ctx);

    size_t smem = (size_t)(MAXR * A_ + 2 * A_ * TJ + A_) * sizeof(float); // ~139.8 KB
    cudaFuncSetAttribute(attn_e_kernel, cudaFuncAttributeMaxDynamicSharedMemorySize, (int)smem);
    attn_e_kernel<<<B_ * CTAS_PER_B, 512, smem>>>(v, attn);

    context_kernel<<<B_ * 64, 512>>>(lstm, ctx);
}

// round 9
// speedup vs baseline: 1.0329x; 1.0329x over previous
#include <cuda_runtime.h>
#include <cuda_fp16.h>
#include <cstdint>

// Shapes (fixed by the problem)
#define B_ 2
#define S_ 1024
#define H_ 512
#define A_ 128

#define CTAS_PER_B 74            // 148 attn CTAs total, 13-14 rows each
#define MAXR 16
#define TJ 128
#define NT 8                     // S_/TJ tiles

// ---------------- scratch (no allocation allowed) ----------------
__device__ float   g_wx  [B_ * S_ * A_];          // [m][a] f32 (1 MB)
__device__ __half2 g_uxth[B_ * (A_ / 2) * S_];    // [b][a2][s], half2 = (a, a+1) pair (0.5 MB)
__device__ float   g_colsum[B_ * S_];

__device__ __forceinline__ __half2 tanh2h(__half2 x) {
    uint32_t xi = *(uint32_t*)&x, yi;
    asm("tanh.approx.f16x2 %0, %1;" : "=r"(yi) : "r"(xi));
    return *(__half2*)&yi;
}

__device__ __forceinline__ void cp16(void* dst_smem, const void* src) {
    uint32_t d = (uint32_t)__cvta_generic_to_shared(dst_smem);
    asm volatile("cp.async.cg.shared.global [%0], [%1], 16;\n" :: "r"(d), "l"(src));
}
#define CP_COMMIT() asm volatile("cp.async.commit_group;\n")
#define CP_WAIT(N)  asm volatile("cp.async.wait_group %0;\n" :: "n"(N))

// ---------------- kernel 1: wx = lstm@w (f32), uxth = pack_f16(lstm@u)^T ----------------
// BM=32 x BN=64, 128 threads, grid (64, 4) = 256 CTAs  (identical to R8 except u-epilogue)
#define BK 16
__global__ __launch_bounds__(128) void gemm_wxux(
    const float* __restrict__ lstm, const float* __restrict__ w, const float* __restrict__ u,
    float* __restrict__ ctx)
{
    __shared__ float As[BK][32];
    __shared__ float Bs[BK][64];
    int tid = threadIdx.x;

    if (blockIdx.x == 0 && blockIdx.y == 0) {      // fused zeroing
        for (int t = tid; t < B_ * S_; t += 128) g_colsum[t] = 0.0f;
        for (int t = tid; t < B_ * H_; t += 128) ctx[t] = 0.0f;
    }

    int m0 = blockIdx.x * 32;                      // 64 blocks over m
    int n0 = blockIdx.y * 64;                      // 0,64 -> w ; 128,192 -> u
    const float* bsrc = (n0 < A_) ? (w + n0) : (u + (n0 - A_));

    int tm = (tid >> 4) * 4;                       // 0..28
    int tn = (tid & 15) * 4;                       // 0..60
    int la_m = tid >> 2;                           // 0..31
    int la_k = (tid & 3) * 4;                      // 0,4,8,12
    int lb_k = tid >> 4;                           // 0..7 (and +8)
    int lb_n = (tid & 15) * 4;                     // 0..60

    float acc[4][4];
#pragma unroll
    for (int i = 0; i < 4; i++)
#pragma unroll
        for (int j = 0; j < 4; j++) acc[i][j] = 0.0f;

    for (int k0 = 0; k0 < H_; k0 += BK) {
        float4 av  = *(const float4*)(lstm + (size_t)(m0 + la_m) * H_ + k0 + la_k);
        float4 bv0 = *(const float4*)(bsrc + (size_t)(k0 + lb_k) * A_ + lb_n);
        float4 bv1 = *(const float4*)(bsrc + (size_t)(k0 + lb_k + 8) * A_ + lb_n);
        __syncthreads();
        As[la_k + 0][la_m] = av.x;
        As[la_k + 1][la_m] = av.y;
        As[la_k + 2][la_m] = av.z;
        As[la_k + 3][la_m] = av.w;
        *(float4*)&Bs[lb_k][lb_n] = bv0;
        *(float4*)&Bs[lb_k + 8][lb_n] = bv1;
        __syncthreads();
#pragma unroll
        for (int kk = 0; kk < BK; kk++) {
            float4 a4 = *(const float4*)&As[kk][tm];
            float4 b4 = *(const float4*)&Bs[kk][tn];
            float am[4] = {a4.x, a4.y, a4.z, a4.w};
            float bn[4] = {b4.x, b4.y, b4.z, b4.w};
#pragma unroll
            for (int i = 0; i < 4; i++)
#pragma unroll
                for (int j = 0; j < 4; j++) acc[i][j] = fmaf(am[i], bn[j], acc[i][j]);
        }
    }

    if (n0 < A_) {
        // wx: row-major f32 [m][a]
#pragma unroll
        for (int i = 0; i < 4; i++) {
            float4 o = make_float4(acc[i][0], acc[i][1], acc[i][2], acc[i][3]);
            *(float4*)(g_wx + (size_t)(m0 + tm + i) * A_ + n0 + tn) = o;
        }
    } else {
        // ux: pack a-pairs to half2, transposed -> g_uxth[b][a2][s]
        int b  = m0 >> 10;
        int s0 = (m0 & (S_ - 1)) + tm;
        int a0 = (n0 - A_) + tn;                   // multiple of 4
        __half2* base = g_uxth + (size_t)b * (A_ / 2) * S_;
#pragma unroll
        for (int i = 0; i < 4; i++) {
            base[(size_t)(a0 / 2 + 0) * S_ + s0 + i] = __floats2half2_rn(acc[i][0], acc[i][1]);
            base[(size_t)(a0 / 2 + 1) * S_ + s0 + i] = __floats2half2_rn(acc[i][2], acc[i][3]);
        }
    }
}

// ---------------- kernel 2: f16-native e kernel, reg softmax, attn + colsum ----------------
// dyn smem: wx_s[16][128] f32 (8KB) + uxh 2x[64][TJ] half2 (2x32KB) + v_h[64] half2 ~72.3KB
__global__ __launch_bounds__(512) void attn_e_kernel(
    const float* __restrict__ v, float* __restrict__ attn_out)
{
    extern __shared__ float sm[];
    float*   wx_s = sm;                            // MAXR*128 f32
    __half2* uxh0 = (__half2*)(wx_s + MAXR * A_);  // 64 rows x TJ half2
    __half2* uxh1 = uxh0 + 64 * TJ;                // 64 rows x TJ half2
    __half2* v_h  = uxh1 + 64 * TJ;                // 64

    int tid  = threadIdx.x;
    int warp = tid >> 5;
    int lane = tid & 31;
    int blk  = blockIdx.x;                         // 148 blocks
    int b    = blk / CTAS_PER_B;
    int t_   = blk % CTAS_PER_B;
    int i0   = (S_ * t_) / CTAS_PER_B;
    int i1   = (S_ * (t_ + 1)) / CTAS_PER_B;
    int nr   = i1 - i0;                            // 13 or 14

    const __half2* uxt_b = g_uxth + (size_t)b * (A_ / 2) * S_;
    int pr = tid >> 3;                             // a2 row 0..63
    int pc = tid & 7;                              // base chunk 0..7

    // prefetch tile 0: 64 rows x 128 half2 = 32KB -> 2048 cp16 (4 per thread)
#pragma unroll
    for (int k = 0; k < 4; k++) {
        int c = 4 * (pc + 8 * k);                  // half2 offset 0..124
        cp16(uxh0 + pr * TJ + c, uxt_b + (size_t)pr * S_ + c);
    }
    CP_COMMIT();

    for (int x = tid; x < nr * (A_ / 4); x += 512) {
        int r = x >> 5, c = x & 31;
        *(float4*)(wx_s + r * A_ + 4 * c) =
            *(const float4*)(g_wx + (size_t)(b * S_ + i0 + r) * A_ + 4 * c);
    }
    if (tid < 64) v_h[tid] = __floats2half2_rn(v[2 * tid], v[2 * tid + 1]);

    bool active = (warp < nr);
    float er[4 * NT];

#pragma unroll
    for (int t = 0; t < NT; t++) {
        __half2* cur = (t & 1) ? uxh1 : uxh0;
        if (t + 1 < NT) {
            __half2* nxt = ((t + 1) & 1) ? uxh1 : uxh0;
            const __half2* src = uxt_b + (size_t)(t + 1) * TJ;
#pragma unroll
            for (int k = 0; k < 4; k++) {
                int c = 4 * (pc + 8 * k);
                cp16(nxt + pr * TJ + c, src + (size_t)pr * S_ + c);
            }
            CP_COMMIT();
            CP_WAIT(1);
        } else {
            CP_WAIT(0);
        }
        __syncthreads();

        if (active) {
            float accf0 = 0.f, accf1 = 0.f, accf2 = 0.f, accf3 = 0.f;
            const float4*  wr = (const float4*)(wx_s + warp * A_);
            const __half2* ub = cur + 4 * lane;    // this thread's 4 j-slots

#pragma unroll
            for (int g = 0; g < 8; g++) {          // spill to f32 every 16 a's
                __half2 h0 = __float2half2_rn(0.f);
                __half2 h1 = __float2half2_rn(0.f);
                __half2 h2 = __float2half2_rn(0.f);
                __half2 h3 = __float2half2_rn(0.f);
#pragma unroll
                for (int q = 0; q < 4; q++) {      // a4 = 4g+q : 4 a's = 2 tile rows
                    int a4 = 4 * g + q;
                    float4 w4 = wr[a4];
                    __half2 wh0 = __floats2half2_rn(w4.x, w4.y);   // a-pair (4a4, 4a4+1)
                    __half2 wh1 = __floats2half2_rn(w4.z, w4.w);   // a-pair (4a4+2, 4a4+3)
                    __half2 vh0 = v_h[2 * a4 + 0];
                    __half2 vh1 = v_h[2 * a4 + 1];
                    const __half2* r0 = ub + (size_t)(2 * a4 + 0) * TJ;
                    const __half2* r1 = ub + (size_t)(2 * a4 + 1) * TJ;
                    __half2 u00 = r0[0], u01 = r0[1], u02 = r0[2], u03 = r0[3];
                    __half2 u10 = r1[0], u11 = r1[1], u12 = r1[2], u13 = r1[3];
                    h0 = __hfma2(tanh2h(__hadd2(wh0, u00)), vh0, h0);
                    h1 = __hfma2(tanh2h(__hadd2(wh0, u01)), vh0, h1);
                    h2 = __hfma2(tanh2h(__hadd2(wh0, u02)), vh0, h2);
                    h3 = __hfma2(tanh2h(__hadd2(wh0, u03)), vh0, h3);
                    h0 = __hfma2(tanh2h(__hadd2(wh1, u10)), vh1, h0);
                    h1 = __hfma2(tanh2h(__hadd2(wh1, u11)), vh1, h1);
                    h2 = __hfma2(tanh2h(__hadd2(wh1, u12)), vh1, h2);
                    h3 = __hfma2(tanh2h(__hadd2(wh1, u13)), vh1, h3);
                }
                float2 f0 = __half22float2(h0);
                float2 f1 = __half22float2(h1);
                float2 f2 = __half22float2(h2);
                float2 f3 = __half22float2(h3);
                accf0 += f0.x + f0.y;
                accf1 += f1.x + f1.y;
                accf2 += f2.x + f2.y;
                accf3 += f3.x + f3.y;
            }
            er[4 * t + 0] = accf0;
            er[4 * t + 1] = accf1;
            er[4 * t + 2] = accf2;
            er[4 * t + 3] = accf3;
        }
        __syncthreads();
    }

    // slots region: uxh0+uxh1 = 64KB contiguous, need nr*1024*4 <= 56KB
    float* slots = (float*)uxh0;
    if (active) {
        float m = er[0];
#pragma unroll
        for (int k = 1; k < 4 * NT; k++) m = fmaxf(m, er[k]);
#pragma unroll
        for (int o = 16; o; o >>= 1) m = fmaxf(m, __shfl_xor_sync(0xffffffffu, m, o));
        float s = 0.f;
#pragma unroll
        for (int k = 0; k < 4 * NT; k++) {
            er[k] = __expf(er[k] - m);
            s += er[k];
        }
#pragma unroll
        for (int o = 16; o; o >>= 1) s += __shfl_xor_sync(0xffffffffu, s, o);
        float inv = 1.0f / s;
        float* orow = attn_out + (size_t)(b * S_ + i0 + warp) * S_;
        float* srow = slots + (size_t)warp * S_;
#pragma unroll
        for (int ti = 0; ti < NT; ti++) {
            float4 o = make_float4(er[4 * ti] * inv, er[4 * ti + 1] * inv,
                                   er[4 * ti + 2] * inv, er[4 * ti + 3] * inv);
            *(float4*)(orow + ti * TJ + 4 * lane) = o;
            *(float4*)(srow + ti * TJ + 4 * lane) = o;
        }
    }
    __syncthreads();

    for (int j = tid; j < S_; j += 512) {
        float s = 0.f;
        for (int r = 0; r < nr; r++) s += slots[(size_t)r * S_ + j];
        atomicAdd(&g_colsum[b * S_ + j], s);
    }
}

// ---------------- kernel 3: context[b,h] = sum_j colsum[b,j] * lstm[b,j,h] ----------------
__global__ __launch_bounds__(512) void context_kernel(
    const float* __restrict__ lstm, float* __restrict__ ctx)
{
    int b  = blockIdx.x >> 6;                      // 2 * 64 blocks
    int j0 = (blockIdx.x & 63) * 16;
    int h  = threadIdx.x;
    __shared__ float cs[16];
    if (threadIdx.x < 16) cs[threadIdx.x] = g_colsum[b * S_ + j0 + threadIdx.x];
    __syncthreads();
    float acc = 0.f;
    const float* lp = lstm + ((size_t)(b * S_ + j0)) * H_ + h;
#pragma unroll
    for (int j = 0; j < 16; j++) acc = fmaf(cs[j], lp[(size_t)j * H_], acc);
    atomicAdd(&ctx[b * H_ + h], acc);
}

// ---------------- launch (single stream, deterministic) ----------------
extern "C" void kernel_launch(void* const* d_in, const int* in_sizes, int n_in,
                              void* d_out, int out_size)
{
    const float* lstm = (const float*)d_in[0];
    const float* w    = (const float*)d_in[1];
    const float* u    = (const float*)d_in[2];
    const float* v    = (const float*)d_in[3];
    float* out  = (float*)d_out;
    float* ctx  = out;                // (B,H) = 1024 floats first
    float* attn = out + B_ * H_;      // (B,S,S) = 2M floats after

    gemm_wxux<<<dim3(64, 4), 128>>>(lstm, w, u, ctx);

    size_t smem = (size_t)(MAXR * A_) * sizeof(float)
                + (size_t)(2 * 64 * TJ + 64) * sizeof(__half2);   // ~72.3 KB
    cudaFuncSetAttribute(attn_e_kernel, cudaFuncAttributeMaxDynamicSharedMemorySize, (int)smem);
    attn_e_kernel<<<B_ * CTAS_PER_B, 512, smem>>>(v, attn);

    context_kernel<<<B_ * 64, 512>>>(lstm, ctx);
}